// round 9
// baseline (speedup 1.0000x reference)
#include <cuda_runtime.h>
#include <cuda_bf16.h>

// Problem shape (fixed by setup_inputs): b=4, h=8, L=256, d=64
#define L_SEQ 256
#define DHEAD 64
#define N_BH  32   // b*h

#define MASK_VAL (-4294967295.0f)   // -2^32 + 1

__global__ __launch_bounds__(256, 2)
void taspd_kernel(const float* __restrict__ Q,
                  const float* __restrict__ K,
                  const float* __restrict__ V,
                  const float* __restrict__ tK,
                  const float* __restrict__ tV,
                  const float* __restrict__ attn_mask,
                  const unsigned char* __restrict__ pad_mask,
                  float* __restrict__ O,
                  float* __restrict__ attnW)
{
    const int bid = blockIdx.x;          // 0 .. 8191
    const int q   = bid & (L_SEQ - 1);
    const int bh  = bid >> 8;            // 0 .. 31
    const int b   = bh >> 3;             // h = 8
    const int tid = threadIdx.x;

    __shared__ float sE[L_SEQ];          // energy, then softmax weights
    __shared__ float sRed[16 * DHEAD];   // phase-2 partial sums
    __shared__ float sScr[8];            // cross-warp reduce scratch

    const float* Qrow  = Q + ((size_t)bh * L_SEQ + q) * DHEAD;
    const float* Kbase = K + (size_t)bh * L_SEQ * DHEAD;
    const float* Vbase = V + (size_t)bh * L_SEQ * DHEAD;
    const size_t tbase = ((size_t)bh * L_SEQ + q) * (size_t)L_SEQ * DHEAD;
    const float* tKrow = tK + tbase;     // [L_SEQ][DHEAD] slice
    const float* tVrow = tV + tbase;

    const int lane16 = tid & 15;         // 16 lanes cover d=64 as float4
    const int grp    = tid >> 4;         // 16 groups cover k

    // ---------------- Phase 1: energy[k] = Q . (K_k + tK_k) ----------------
    // 8 k-rows per iteration, all 16 loads issued before any math (MLP=16/thr).
    {
        float4 q4 = reinterpret_cast<const float4*>(Qrow)[lane16];
        #pragma unroll
        for (int it = 0; it < 2; ++it) {
            const int kb = it * 128 + grp;
            float4 kv[8], tk[8];
            #pragma unroll
            for (int j = 0; j < 8; ++j) {
                const int k = kb + j * 16;
                kv[j] = reinterpret_cast<const float4*>(Kbase + (size_t)k * DHEAD)[lane16];
                tk[j] = __ldcs(reinterpret_cast<const float4*>(tKrow + (size_t)k * DHEAD) + lane16);
            }
            float p[8];
            #pragma unroll
            for (int j = 0; j < 8; ++j) {
                p[j] = q4.x * (kv[j].x + tk[j].x) + q4.y * (kv[j].y + tk[j].y)
                     + q4.z * (kv[j].z + tk[j].z) + q4.w * (kv[j].w + tk[j].w);
            }
            // reduce across the 16-lane segment (xor stays inside segment)
            #pragma unroll
            for (int off = 8; off; off >>= 1) {
                #pragma unroll
                for (int j = 0; j < 8; ++j)
                    p[j] += __shfl_xor_sync(0xffffffffu, p[j], off);
            }
            if (lane16 == 0) {
                #pragma unroll
                for (int j = 0; j < 8; ++j) {
                    const int k = kb + j * 16;
                    float e = p[j] * 0.125f + attn_mask[q * L_SEQ + k];   // /sqrt(64)
                    if (pad_mask[b * L_SEQ + k]) e = MASK_VAL;
                    sE[k] = e;
                }
            }
        }
    }
    __syncthreads();

    // ---------------- Softmax over k (tid owns k = tid) ----------------
    float e = sE[tid];
    float m = e;
    #pragma unroll
    for (int off = 16; off; off >>= 1)
        m = fmaxf(m, __shfl_xor_sync(0xffffffffu, m, off));
    if ((tid & 31) == 0) sScr[tid >> 5] = m;
    __syncthreads();
    m = sScr[0];
    #pragma unroll
    for (int i = 1; i < 8; ++i) m = fmaxf(m, sScr[i]);
    __syncthreads();                     // protect sScr before reuse

    float ex = __expf(e - m);
    float s = ex;
    #pragma unroll
    for (int off = 16; off; off >>= 1)
        s += __shfl_xor_sync(0xffffffffu, s, off);
    if ((tid & 31) == 0) sScr[tid >> 5] = s;
    __syncthreads();
    s = sScr[0];
    #pragma unroll
    for (int i = 1; i < 8; ++i) s += sScr[i];

    const float w = ex / s;
    sE[tid] = w;                          // own element: no race
    if (attnW)
        __stcs(&attnW[((size_t)bh * L_SEQ + q) * L_SEQ + tid], w);
    __syncthreads();

    // ---------------- Phase 2: O[d] = sum_k w_k * (V_k[d] + tV_k[d]) -------
    // 8 k-rows per iteration: 16 independent loads in flight (MLP=16/thr).
    {
        float4 acc = make_float4(0.f, 0.f, 0.f, 0.f);
        #pragma unroll
        for (int it = 0; it < 2; ++it) {
            const int kb = it * 128 + grp;          // grp in [0,16)
            float4 v[8], tv[8];
            #pragma unroll
            for (int j = 0; j < 8; ++j) {
                const int k = kb + j * 16;
                v[j]  = reinterpret_cast<const float4*>(Vbase + (size_t)k * DHEAD)[lane16];
                tv[j] = __ldcs(reinterpret_cast<const float4*>(tVrow + (size_t)k * DHEAD) + lane16);
            }
            #pragma unroll
            for (int j = 0; j < 8; ++j) {
                const float wk = sE[kb + j * 16];
                acc.x += wk * (v[j].x + tv[j].x);
                acc.y += wk * (v[j].y + tv[j].y);
                acc.z += wk * (v[j].z + tv[j].z);
                acc.w += wk * (v[j].w + tv[j].w);
            }
        }
        reinterpret_cast<float4*>(sRed + grp * DHEAD)[lane16] = acc;
        __syncthreads();
        if (tid < DHEAD) {
            float o = 0.f;
            #pragma unroll
            for (int g = 0; g < 16; ++g) o += sRed[g * DHEAD + tid];
            O[((size_t)bh * L_SEQ + q) * DHEAD + tid] = o;
        }
    }
}

extern "C" void kernel_launch(void* const* d_in, const int* in_sizes, int n_in,
                              void* d_out, int out_size)
{
    const float*         Q  = (const float*)d_in[0];
    const float*         K  = (const float*)d_in[1];
    const float*         V  = (const float*)d_in[2];
    const float*         tK = (const float*)d_in[3];
    const float*         tV = (const float*)d_in[4];
    const float*         am = (const float*)d_in[5];
    const unsigned char* pm = (const unsigned char*)d_in[6];

    float* O = (float*)d_out;
    const int o_elems    = N_BH * L_SEQ * DHEAD;   // 2,097,152
    const int attn_elems = N_BH * L_SEQ * L_SEQ;   // 8,388,608
    float* attnW = (out_size >= o_elems + attn_elems) ? O + o_elems : nullptr;

    taspd_kernel<<<N_BH * L_SEQ, 256>>>(Q, K, V, tK, tV, am, pm, O, attnW);
}

// round 12
// speedup vs baseline: 1.0301x; 1.0301x over previous
#include <cuda_runtime.h>
#include <cuda_bf16.h>

// Problem shape (fixed by setup_inputs): b=4, h=8, L=256, d=64
#define L_SEQ 256
#define DHEAD 64
#define N_BH  32   // b*h

#define MASK_VAL (-4294967295.0f)   // -2^32 + 1

__global__ __launch_bounds__(128, 6)
void taspd_kernel(const float* __restrict__ Q,
                  const float* __restrict__ K,
                  const float* __restrict__ V,
                  const float* __restrict__ tK,
                  const float* __restrict__ tV,
                  const float* __restrict__ attn_mask,
                  const unsigned char* __restrict__ pad_mask,
                  float* __restrict__ O,
                  float* __restrict__ attnW)
{
    const int bid = blockIdx.x;          // 0 .. 8191
    const int q   = bid & (L_SEQ - 1);
    const int bh  = bid >> 8;            // 0 .. 31
    const int b   = bh >> 3;             // h = 8
    const int tid = threadIdx.x;         // 0 .. 127

    __shared__ float sE[L_SEQ];          // energy, then softmax weights
    __shared__ float sRed[8 * DHEAD];    // phase-2 partial sums (8 groups)
    __shared__ float sScr[4];            // cross-warp reduce scratch (4 warps)

    const float* Qrow  = Q + ((size_t)bh * L_SEQ + q) * DHEAD;
    const float* Kbase = K + (size_t)bh * L_SEQ * DHEAD;
    const float* Vbase = V + (size_t)bh * L_SEQ * DHEAD;
    const size_t tbase = ((size_t)bh * L_SEQ + q) * (size_t)L_SEQ * DHEAD;
    const float* tKrow = tK + tbase;     // [L_SEQ][DHEAD] slice
    const float* tVrow = tV + tbase;

    const int lane16 = tid & 15;         // 16 lanes cover d=64 as float4
    const int grp    = tid >> 4;         // 8 groups cover k

    // ---------------- Phase 1: energy[k] = Q . (K_k + tK_k) ----------------
    // 4 k-rows per group per iteration: 8 loads batched (MLP=8/thr).
    {
        float4 q4 = reinterpret_cast<const float4*>(Qrow)[lane16];
        #pragma unroll 2
        for (int it = 0; it < 8; ++it) {
            const int kb = it * 32 + grp;        // rows kb, kb+8, kb+16, kb+24
            float4 kv[4], tk[4];
            #pragma unroll
            for (int j = 0; j < 4; ++j) {
                const int k = kb + j * 8;
                kv[j] = reinterpret_cast<const float4*>(Kbase + (size_t)k * DHEAD)[lane16];
                tk[j] = __ldcs(reinterpret_cast<const float4*>(tKrow + (size_t)k * DHEAD) + lane16);
            }
            float p[4];
            #pragma unroll
            for (int j = 0; j < 4; ++j) {
                p[j] = q4.x * (kv[j].x + tk[j].x) + q4.y * (kv[j].y + tk[j].y)
                     + q4.z * (kv[j].z + tk[j].z) + q4.w * (kv[j].w + tk[j].w);
            }
            // reduce across the 16-lane segment (xor stays inside segment)
            #pragma unroll
            for (int off = 8; off; off >>= 1) {
                #pragma unroll
                for (int j = 0; j < 4; ++j)
                    p[j] += __shfl_xor_sync(0xffffffffu, p[j], off);
            }
            if (lane16 == 0) {
                #pragma unroll
                for (int j = 0; j < 4; ++j) {
                    const int k = kb + j * 8;
                    float e = p[j] * 0.125f + attn_mask[q * L_SEQ + k];   // /sqrt(64)
                    if (pad_mask[b * L_SEQ + k]) e = MASK_VAL;
                    sE[k] = e;
                }
            }
        }
    }
    __syncthreads();

    // ---------------- Softmax over k (tid owns k = tid and tid+128) --------
    float e0 = sE[tid];
    float e1 = sE[tid + 128];
    float m = fmaxf(e0, e1);
    #pragma unroll
    for (int off = 16; off; off >>= 1)
        m = fmaxf(m, __shfl_xor_sync(0xffffffffu, m, off));
    if ((tid & 31) == 0) sScr[tid >> 5] = m;
    __syncthreads();
    m = fmaxf(fmaxf(sScr[0], sScr[1]), fmaxf(sScr[2], sScr[3]));
    __syncthreads();                     // protect sScr before reuse

    float ex0 = __expf(e0 - m);
    float ex1 = __expf(e1 - m);
    float s = ex0 + ex1;
    #pragma unroll
    for (int off = 16; off; off >>= 1)
        s += __shfl_xor_sync(0xffffffffu, s, off);
    if ((tid & 31) == 0) sScr[tid >> 5] = s;
    __syncthreads();
    s = (sScr[0] + sScr[1]) + (sScr[2] + sScr[3]);

    const float inv = 1.0f / s;
    const float w0 = ex0 * inv;
    const float w1 = ex1 * inv;
    sE[tid]       = w0;                  // own elements: no race
    sE[tid + 128] = w1;
    if (attnW) {
        float* aw = attnW + ((size_t)bh * L_SEQ + q) * L_SEQ;
        __stcs(aw + tid, w0);
        __stcs(aw + tid + 128, w1);
    }
    __syncthreads();

    // ---------------- Phase 2: O[d] = sum_k w_k * (V_k[d] + tV_k[d]) -------
    // 4 k-rows per group per iteration: 8 loads batched (MLP=8/thr).
    {
        float4 acc = make_float4(0.f, 0.f, 0.f, 0.f);
        #pragma unroll 2
        for (int it = 0; it < 8; ++it) {
            const int kb = it * 32 + grp;
            float4 v[4], tv[4];
            #pragma unroll
            for (int j = 0; j < 4; ++j) {
                const int k = kb + j * 8;
                v[j]  = reinterpret_cast<const float4*>(Vbase + (size_t)k * DHEAD)[lane16];
                tv[j] = __ldcs(reinterpret_cast<const float4*>(tVrow + (size_t)k * DHEAD) + lane16);
            }
            #pragma unroll
            for (int j = 0; j < 4; ++j) {
                const float wk = sE[kb + j * 8];
                acc.x += wk * (v[j].x + tv[j].x);
                acc.y += wk * (v[j].y + tv[j].y);
                acc.z += wk * (v[j].z + tv[j].z);
                acc.w += wk * (v[j].w + tv[j].w);
            }
        }
        reinterpret_cast<float4*>(sRed + grp * DHEAD)[lane16] = acc;
        __syncthreads();
        if (tid < DHEAD) {
            float o = 0.f;
            #pragma unroll
            for (int g = 0; g < 8; ++g) o += sRed[g * DHEAD + tid];
            O[((size_t)bh * L_SEQ + q) * DHEAD + tid] = o;
        }
    }
}

extern "C" void kernel_launch(void* const* d_in, const int* in_sizes, int n_in,
                              void* d_out, int out_size)
{
    const float*         Q  = (const float*)d_in[0];
    const float*         K  = (const float*)d_in[1];
    const float*         V  = (const float*)d_in[2];
    const float*         tK = (const float*)d_in[3];
    const float*         tV = (const float*)d_in[4];
    const float*         am = (const float*)d_in[5];
    const unsigned char* pm = (const unsigned char*)d_in[6];

    float* O = (float*)d_out;
    const int o_elems    = N_BH * L_SEQ * DHEAD;   // 2,097,152
    const int attn_elems = N_BH * L_SEQ * L_SEQ;   // 8,388,608
    float* attnW = (out_size >= o_elems + attn_elems) ? O + o_elems : nullptr;

    taspd_kernel<<<N_BH * L_SEQ, 128>>>(Q, K, V, tK, tV, am, pm, O, attnW);
}